// round 1
// baseline (speedup 1.0000x reference)
#include <cuda_runtime.h>
#include <math.h>
#include <stdint.h>

// Problem constants
#define BATCH 2
#define NB    9216          // H*W per batch (96*96)
#define NPIX  (BATCH * NB)  // 18432
#define CIN   384
#define C1    256
#define C2    128
#define MASK_THR 0.2f

// Scratch (device globals: no allocations allowed)
__device__ float g_h1[(size_t)C1 * NPIX];      // [o][n]  (k-major for GEMM2)
__device__ float g_feat[(size_t)NPIX * C2];    // [n][c]
__device__ float g_rf[(size_t)NPIX * C2];      // [n][c]  normalized, row-major
__device__ float g_rft[(size_t)BATCH * C2 * NB]; // [b][c][hw]  normalized, k-major
__device__ int   g_nn[NPIX];                   // within-batch index of 2nd top sim

// ---------------------------------------------------------------------------
// GEMM1: g_h1[o][n] = relu( sum_k W1[o][k] * X[b][k][hw] + b1[o] )
// Tiles: BM(o)=64, BN(n)=64, BK=16. 256 threads, 4x4 per thread.
// ---------------------------------------------------------------------------
__global__ void gemm1_kernel(const float* __restrict__ X,
                             const float* __restrict__ W1,
                             const float* __restrict__ b1v) {
    __shared__ float Ws[64 * 16];   // [o][k]
    __shared__ float Xs[16 * 64];   // [k][n]
    const int t  = threadIdx.x;
    const int tx = t & 15, ty = t >> 4;
    const int n0 = blockIdx.x * 64;
    const int o0 = blockIdx.y * 64;
    const int b  = n0 / NB;
    const int hw0 = n0 % NB;
    const float* Xb = X + (size_t)b * CIN * NB;

    float acc[4][4];
#pragma unroll
    for (int i = 0; i < 4; i++)
#pragma unroll
        for (int j = 0; j < 4; j++) acc[i][j] = 0.f;

    const int lo = t >> 2, lq = t & 3;     // W-load: o, k-quad
    const int lk = t >> 4, ln4 = t & 15;   // X-load: k, n-quad

    for (int k0 = 0; k0 < CIN; k0 += 16) {
        float4 w = *(const float4*)&W1[(size_t)(o0 + lo) * CIN + k0 + lq * 4];
        *(float4*)&Ws[lo * 16 + lq * 4] = w;
        float4 x = *(const float4*)&Xb[(size_t)(k0 + lk) * NB + hw0 + ln4 * 4];
        *(float4*)&Xs[lk * 64 + ln4 * 4] = x;
        __syncthreads();
#pragma unroll
        for (int k4 = 0; k4 < 4; k4++) {
            float4 w0 = *(const float4*)&Ws[(ty * 4 + 0) * 16 + k4 * 4];
            float4 w1 = *(const float4*)&Ws[(ty * 4 + 1) * 16 + k4 * 4];
            float4 w2 = *(const float4*)&Ws[(ty * 4 + 2) * 16 + k4 * 4];
            float4 w3 = *(const float4*)&Ws[(ty * 4 + 3) * 16 + k4 * 4];
            const float* wp0 = (const float*)&w0;
            const float* wp1 = (const float*)&w1;
            const float* wp2 = (const float*)&w2;
            const float* wp3 = (const float*)&w3;
#pragma unroll
            for (int kk = 0; kk < 4; kk++) {
                float4 xv = *(const float4*)&Xs[(k4 * 4 + kk) * 64 + tx * 4];
                float a0 = wp0[kk], a1 = wp1[kk], a2 = wp2[kk], a3 = wp3[kk];
                acc[0][0] += a0 * xv.x; acc[0][1] += a0 * xv.y; acc[0][2] += a0 * xv.z; acc[0][3] += a0 * xv.w;
                acc[1][0] += a1 * xv.x; acc[1][1] += a1 * xv.y; acc[1][2] += a1 * xv.z; acc[1][3] += a1 * xv.w;
                acc[2][0] += a2 * xv.x; acc[2][1] += a2 * xv.y; acc[2][2] += a2 * xv.z; acc[2][3] += a2 * xv.w;
                acc[3][0] += a3 * xv.x; acc[3][1] += a3 * xv.y; acc[3][2] += a3 * xv.z; acc[3][3] += a3 * xv.w;
            }
        }
        __syncthreads();
    }
#pragma unroll
    for (int i = 0; i < 4; i++) {
        int o = o0 + ty * 4 + i;
        float bias = b1v[o];
        float4 r;
        r.x = fmaxf(acc[i][0] + bias, 0.f);
        r.y = fmaxf(acc[i][1] + bias, 0.f);
        r.z = fmaxf(acc[i][2] + bias, 0.f);
        r.w = fmaxf(acc[i][3] + bias, 0.f);
        *(float4*)&g_h1[(size_t)o * NPIX + n0 + tx * 4] = r;
    }
}

// ---------------------------------------------------------------------------
// GEMM2: g_feat[n][o] = sum_k W2[o][k] * g_h1[k][n] + b2[o]
// ---------------------------------------------------------------------------
__global__ void gemm2_kernel(const float* __restrict__ W2,
                             const float* __restrict__ b2v) {
    __shared__ float Ws[64 * 16];   // [o][k]
    __shared__ float Hs[16 * 64];   // [k][n]
    const int t  = threadIdx.x;
    const int tx = t & 15, ty = t >> 4;
    const int n0 = blockIdx.x * 64;
    const int o0 = blockIdx.y * 64;

    float acc[4][4];
#pragma unroll
    for (int i = 0; i < 4; i++)
#pragma unroll
        for (int j = 0; j < 4; j++) acc[i][j] = 0.f;

    const int lo = t >> 2, lq = t & 3;
    const int lk = t >> 4, ln4 = t & 15;

    for (int k0 = 0; k0 < C1; k0 += 16) {
        float4 w = *(const float4*)&W2[(size_t)(o0 + lo) * C1 + k0 + lq * 4];
        *(float4*)&Ws[lo * 16 + lq * 4] = w;
        float4 h = *(const float4*)&g_h1[(size_t)(k0 + lk) * NPIX + n0 + ln4 * 4];
        *(float4*)&Hs[lk * 64 + ln4 * 4] = h;
        __syncthreads();
#pragma unroll
        for (int k4 = 0; k4 < 4; k4++) {
            float4 w0 = *(const float4*)&Ws[(ty * 4 + 0) * 16 + k4 * 4];
            float4 w1 = *(const float4*)&Ws[(ty * 4 + 1) * 16 + k4 * 4];
            float4 w2 = *(const float4*)&Ws[(ty * 4 + 2) * 16 + k4 * 4];
            float4 w3 = *(const float4*)&Ws[(ty * 4 + 3) * 16 + k4 * 4];
            const float* wp0 = (const float*)&w0;
            const float* wp1 = (const float*)&w1;
            const float* wp2 = (const float*)&w2;
            const float* wp3 = (const float*)&w3;
#pragma unroll
            for (int kk = 0; kk < 4; kk++) {
                float4 xv = *(const float4*)&Hs[(k4 * 4 + kk) * 64 + tx * 4];
                float a0 = wp0[kk], a1 = wp1[kk], a2 = wp2[kk], a3 = wp3[kk];
                acc[0][0] += a0 * xv.x; acc[0][1] += a0 * xv.y; acc[0][2] += a0 * xv.z; acc[0][3] += a0 * xv.w;
                acc[1][0] += a1 * xv.x; acc[1][1] += a1 * xv.y; acc[1][2] += a1 * xv.z; acc[1][3] += a1 * xv.w;
                acc[2][0] += a2 * xv.x; acc[2][1] += a2 * xv.y; acc[2][2] += a2 * xv.z; acc[2][3] += a2 * xv.w;
                acc[3][0] += a3 * xv.x; acc[3][1] += a3 * xv.y; acc[3][2] += a3 * xv.z; acc[3][3] += a3 * xv.w;
            }
        }
        __syncthreads();
    }
    float bias[4];
#pragma unroll
    for (int i = 0; i < 4; i++) bias[i] = b2v[o0 + ty * 4 + i];
#pragma unroll
    for (int j = 0; j < 4; j++) {
        int n = n0 + tx * 4 + j;
        float4 r;
        r.x = acc[0][j] + bias[0];
        r.y = acc[1][j] + bias[1];
        r.z = acc[2][j] + bias[2];
        r.w = acc[3][j] + bias[3];
        *(float4*)&g_feat[(size_t)n * C2 + o0 + ty * 4] = r;
    }
}

// ---------------------------------------------------------------------------
// Normalize: rf = feat / max(||feat||, 1e-12); also write k-major copy rft.
// One block (128 threads) per pixel.
// ---------------------------------------------------------------------------
__global__ void normalize_kernel() {
    const int n = blockIdx.x;
    const int c = threadIdx.x;
    float v = g_feat[(size_t)n * C2 + c];
    float s = v * v;
#pragma unroll
    for (int off = 16; off; off >>= 1) s += __shfl_xor_sync(0xffffffffu, s, off);
    __shared__ float ws[4];
    if ((c & 31) == 0) ws[c >> 5] = s;
    __syncthreads();
    float tot = ws[0] + ws[1] + ws[2] + ws[3];
    float norm = sqrtf(tot);
    float nf = v / fmaxf(norm, 1e-12f);
    g_rf[(size_t)n * C2 + c] = nf;
    int b = n / NB, hw = n % NB;
    g_rft[((size_t)b * C2 + c) * NB + hw] = nf;
}

// ---------------------------------------------------------------------------
// Similarity top-2 (argmax machinery). For each row i (per batch), find the
// index of the 2nd-largest sim value over all j (self included), with jax
// top_k tie-breaking (equal values -> lower index first).
// Block: 64 i-rows, scans all 9216 j in 64-col tiles. 256 threads, 4x4/thread.
// Smem: Ri[128][64] (full K, k-major) + Rj[64][64] (half-K chunks) = 48 KB.
// ---------------------------------------------------------------------------
__device__ __forceinline__ void ins2(float v, int j,
                                     float& v1, int& i1, float& v2, int& i2) {
    if (v > v1 || (v == v1 && j < i1)) {
        v2 = v1; i2 = i1; v1 = v; i1 = j;
    } else if (v > v2 || (v == v2 && j < i2)) {
        v2 = v; i2 = j;
    }
}

__global__ void sim_kernel() {
    __shared__ float Ri[128 * 64];  // [k][i]
    __shared__ float Rj[64 * 64];   // [k_local][j]
    const int t  = threadIdx.x;
    const int tx = t & 15, ty = t >> 4;
    const int b  = blockIdx.y;
    const int i0 = blockIdx.x * 64;
    const float* rftb = g_rft + (size_t)b * C2 * NB;

    // Load Ri tile (k-major, coalesced along hw)
#pragma unroll
    for (int it = 0; it < 8; it++) {
        int f = t + it * 256;
        int k = f >> 4, n4 = f & 15;
        *(float4*)&Ri[k * 64 + n4 * 4] =
            *(const float4*)&rftb[(size_t)k * NB + i0 + n4 * 4];
    }

    float v1[4], v2[4]; int i1[4], i2[4];
#pragma unroll
    for (int i = 0; i < 4; i++) {
        v1[i] = -INFINITY; v2[i] = -INFINITY;
        i1[i] = 0x7fffffff; i2[i] = 0x7fffffff;
    }
    __syncthreads();

    for (int jt = 0; jt < NB / 64; jt++) {
        const int j0 = jt * 64;
        float acc[4][4];
#pragma unroll
        for (int i = 0; i < 4; i++)
#pragma unroll
            for (int j = 0; j < 4; j++) acc[i][j] = 0.f;

#pragma unroll
        for (int kc = 0; kc < 2; kc++) {
#pragma unroll
            for (int it = 0; it < 4; it++) {
                int f = t + it * 256;
                int k = f >> 4, n4 = f & 15;
                *(float4*)&Rj[k * 64 + n4 * 4] =
                    *(const float4*)&rftb[(size_t)(kc * 64 + k) * NB + j0 + n4 * 4];
            }
            __syncthreads();
#pragma unroll 8
            for (int k = 0; k < 64; k++) {
                float4 a  = *(const float4*)&Ri[(kc * 64 + k) * 64 + ty * 4];
                float4 bb = *(const float4*)&Rj[k * 64 + tx * 4];
                acc[0][0] += a.x * bb.x; acc[0][1] += a.x * bb.y; acc[0][2] += a.x * bb.z; acc[0][3] += a.x * bb.w;
                acc[1][0] += a.y * bb.x; acc[1][1] += a.y * bb.y; acc[1][2] += a.y * bb.z; acc[1][3] += a.y * bb.w;
                acc[2][0] += a.z * bb.x; acc[2][1] += a.z * bb.y; acc[2][2] += a.z * bb.z; acc[2][3] += a.z * bb.w;
                acc[3][0] += a.w * bb.x; acc[3][1] += a.w * bb.y; acc[3][2] += a.w * bb.z; acc[3][3] += a.w * bb.w;
            }
            __syncthreads();
        }
#pragma unroll
        for (int i = 0; i < 4; i++)
#pragma unroll
            for (int j = 0; j < 4; j++)
                ins2(acc[i][j], j0 + tx * 4 + j, v1[i], i1[i], v2[i], i2[i]);
    }

    // Cross-thread merge per row (reuse Ri smem: 16 KB needed, 32 KB there)
    float* svals = Ri;
    int*   sidx  = (int*)(Ri + 2048);
#pragma unroll
    for (int i = 0; i < 4; i++) {
        int row = ty * 4 + i;
        svals[row * 32 + tx * 2 + 0] = v1[i];
        svals[row * 32 + tx * 2 + 1] = v2[i];
        sidx [row * 32 + tx * 2 + 0] = i1[i];
        sidx [row * 32 + tx * 2 + 1] = i2[i];
    }
    __syncthreads();
    if (t < 64) {
        float bv1 = -INFINITY, bv2 = -INFINITY;
        int bi1 = 0x7fffffff, bi2 = 0x7fffffff;
        for (int c = 0; c < 32; c++)
            ins2(svals[t * 32 + c], sidx[t * 32 + c], bv1, bi1, bv2, bi2);
        g_nn[b * NB + i0 + t] = bi2;
    }
}

// ---------------------------------------------------------------------------
// Distance + mask: exact recomputation from fp32 rf (matches reference math).
// One warp per row. Output: out[0:NPIX]=mask, out[NPIX:2*NPIX]=distance.
// ---------------------------------------------------------------------------
__global__ void dist_kernel(float* __restrict__ out) {
    const int gw   = (int)((blockIdx.x * blockDim.x + threadIdx.x) >> 5);
    const int lane = threadIdx.x & 31;
    if (gw >= NPIX) return;
    const int b  = gw / NB;
    const int nn = g_nn[gw];
    const float* a = g_rf + (size_t)gw * C2;
    const float* c = g_rf + (size_t)(b * NB + nn) * C2;
    float4 av = *(const float4*)&a[lane * 4];
    float4 cv = *(const float4*)&c[lane * 4];
    float dx = av.x - cv.x, dy = av.y - cv.y, dz = av.z - cv.z, dw = av.w - cv.w;
    float s = dx * dx + dy * dy + dz * dz + dw * dw;
#pragma unroll
    for (int off = 16; off; off >>= 1) s += __shfl_xor_sync(0xffffffffu, s, off);
    if (lane == 0) {
        float d = sqrtf(s);
        out[NPIX + gw] = d;
        out[gw] = (d > MASK_THR) ? 1.0f : 0.0f;
    }
}

// ---------------------------------------------------------------------------
extern "C" void kernel_launch(void* const* d_in, const int* in_sizes, int n_in,
                              void* d_out, int out_size) {
    const float* features = (const float*)d_in[0];
    const float* W1 = (const float*)d_in[1];
    const float* b1 = (const float*)d_in[2];
    const float* W2 = (const float*)d_in[3];
    const float* b2 = (const float*)d_in[4];
    float* out = (float*)d_out;

    gemm1_kernel<<<dim3(NPIX / 64, C1 / 64), 256>>>(features, W1, b1);
    gemm2_kernel<<<dim3(NPIX / 64, C2 / 64), 256>>>(W2, b2);
    normalize_kernel<<<NPIX, 128>>>();
    sim_kernel<<<dim3(NB / 64, BATCH), 256>>>();
    dist_kernel<<<(NPIX * 32 + 255) / 256, 256>>>(out);
}